// round 3
// baseline (speedup 1.0000x reference)
#include <cuda_runtime.h>
#include <cuda_pipeline.h>
#include <math.h>

// ChannelAttention fused kernel — R3: cp.async (LDGSTS) staged pipeline.
// x  : [B=8, O=8, S=32, C=64, 32, 32] fp32 (512 MB, streamed once)
// w1 : [8,64,64], w2 : [8,64,64] fp32 (L2-resident)
// out: [B,O,S,C] fp32
//
// One CTA per (b,o,s) = 256 KB of x. Pipeline: 16 stages of 16 KB (4 channels),
// depth 4 (64 KB smem). cp.async carries the DRAM latency (no result regs),
// 16 warps consume each stage: warp w -> local channel w/4, quarter w%4.

#define C_DIM    64
#define HW_DIM   1024
#define O_DIM    8
#define S_DIM    32
#define THREADS  512
#define STAGE_CH 4
#define STAGE_F4 1024          // float4 per stage = 4 ch * 256
#define NSTAGES  16
#define DEPTH    4

__global__ __launch_bounds__(THREADS, 3)
void channel_attention_kernel(const float* __restrict__ x,
                              const float* __restrict__ w1,
                              const float* __restrict__ w2,
                              float* __restrict__ out)
{
    extern __shared__ float4 sbuf[];            // DEPTH * STAGE_F4 float4 = 64 KB
    __shared__ float psum[C_DIM][4];            // per-(channel, quarter) partial sums
    __shared__ float pmx [C_DIM][4];            // per-(channel, quarter) partial maxes
    __shared__ float pm[C_DIM], px[C_DIM], hs[C_DIM];

    const int blk  = blockIdx.x;                // b*O*S + o*S + s
    const int o    = (blk / S_DIM) % O_DIM;
    const int tid  = threadIdx.x;
    const int lane = tid & 31;
    const int wid  = tid >> 5;                  // 16 warps
    const int lc   = wid >> 2;                  // local channel within stage (0..3)
    const int q    = wid & 3;                   // quarter of channel (0..3)

    const float4* src = reinterpret_cast<const float4*>(x)
                      + (size_t)blk * (C_DIM * HW_DIM / 4);

    // ---- prologue: fill DEPTH stages ----
    #pragma unroll
    for (int s = 0; s < DEPTH; ++s) {
        float4*       dst = sbuf + s * STAGE_F4;
        const float4* g   = src  + s * STAGE_F4;
        __pipeline_memcpy_async(dst + tid,       g + tid,       16);
        __pipeline_memcpy_async(dst + tid + 512, g + tid + 512, 16);
        __pipeline_commit();
    }

    // ---- main pipeline ----
    for (int s = 0; s < NSTAGES; ++s) {
        __pipeline_wait_prior(DEPTH - 1);       // stage s landed
        __syncthreads();                        // make cp.async writes visible to all

        const float4* p = sbuf + (s % DEPTH) * STAGE_F4 + lc * 256 + q * 64;
        float4 a = p[lane];
        float4 b = p[lane + 32];
        float sm = ((a.x + a.y) + (a.z + a.w)) + ((b.x + b.y) + (b.z + b.w));
        float mx = fmaxf(fmaxf(fmaxf(a.x, a.y), fmaxf(a.z, a.w)),
                         fmaxf(fmaxf(b.x, b.y), fmaxf(b.z, b.w)));
        #pragma unroll
        for (int off = 16; off > 0; off >>= 1) {
            sm += __shfl_xor_sync(0xFFFFFFFFu, sm, off);
            mx  = fmaxf(mx, __shfl_xor_sync(0xFFFFFFFFu, mx, off));
        }
        if (lane == 0) {
            psum[s * STAGE_CH + lc][q] = sm;    // each (c,q) written exactly once
            pmx [s * STAGE_CH + lc][q] = mx;
        }
        __syncthreads();                        // all warps done reading this slot

        if (s + DEPTH < NSTAGES) {
            float4*       dst = sbuf + (s % DEPTH) * STAGE_F4;
            const float4* g   = src  + (s + DEPTH) * STAGE_F4;
            __pipeline_memcpy_async(dst + tid,       g + tid,       16);
            __pipeline_memcpy_async(dst + tid + 512, g + tid + 512, 16);
        }
        __pipeline_commit();                    // commit every iter (may be empty)
    }

    // ---- combine quarters ----
    if (tid < C_DIM) {
        float s4 = (psum[tid][0] + psum[tid][1]) + (psum[tid][2] + psum[tid][3]);
        float m4 = fmaxf(fmaxf(pmx[tid][0], pmx[tid][1]),
                         fmaxf(pmx[tid][2], pmx[tid][3]));
        pm[tid] = s4 * (1.0f / (float)HW_DIM);
        px[tid] = m4;
    }
    __syncthreads();

    // ---- FC1 + relu ----
    if (tid < C_DIM) {
        const float* w1r = w1 + ((size_t)o * C_DIM + tid) * C_DIM;
        float am = 0.0f, ax = 0.0f;
        #pragma unroll
        for (int c = 0; c < C_DIM; ++c) {
            float w = __ldg(w1r + c);
            am = fmaf(pm[c], w, am);
            ax = fmaf(px[c], w, ax);
        }
        hs[tid] = fmaxf(am, 0.0f) + fmaxf(ax, 0.0f);
    }
    __syncthreads();

    // ---- FC2 + sigmoid (linearity: single pass over summed hidden) ----
    if (tid < C_DIM) {
        const float* w2r = w2 + ((size_t)o * C_DIM + tid) * C_DIM;
        float a = 0.0f;
        #pragma unroll
        for (int h = 0; h < C_DIM; ++h)
            a = fmaf(hs[h], __ldg(w2r + h), a);
        out[(size_t)blk * C_DIM + tid] = 1.0f / (1.0f + __expf(-a));
    }
}

extern "C" void kernel_launch(void* const* d_in, const int* in_sizes, int n_in,
                              void* d_out, int out_size)
{
    const float* x  = (const float*)d_in[0];
    const float* w1 = (const float*)d_in[1];
    const float* w2 = (const float*)d_in[2];
    float* out = (float*)d_out;

    static_assert(DEPTH * STAGE_F4 * sizeof(float4) == 65536, "smem size");
    cudaFuncSetAttribute(channel_attention_kernel,
                         cudaFuncAttributeMaxDynamicSharedMemorySize, 65536);

    channel_attention_kernel<<<2048, THREADS, 65536>>>(x, w1, w2, out);
}